// round 7
// baseline (speedup 1.0000x reference)
#include <cuda_runtime.h>
#include <cuda_fp16.h>

#define NCFG 21

__constant__ int c_kh[NCFG] = {74,60,49,93,76,62, 148,120,98,186,152,124,
                               235,192,156,296,241,197,373,304,248};
__constant__ int c_kw[NCFG] = {49,60,74,62,76,93, 98,120,148,124,152,186,
                               156,192,235,197,241,296,248,304,373};
__constant__ int c_off[NCFG] = {0,3626,7226,10852,16618,22394,
                                28160,42664,57064,71568,94632,117736,
                                140800,177460,214324,250984,309296,367377,
                                425689,518193,610609};
// total area = 703113 pixels; scratch: [cfg][bk(32)][pixel], half4 packed in float2
#define TOTAL_AGG 22499616
__device__ float2 g_aggh[TOTAL_AGG];   // 180 MB

// x padded to float4: [b][y][x] (8*448*448 = 1,605,632 float4 = 25.7MB)
#define XN 1605632
__device__ float4 g_x4[XN];

// Tap tables
__device__ float4 g_tyw[NCFG][224];
__device__ int4   g_tyo[NCFG][224];
__device__ float4 g_txw[NCFG][224];
__device__ int4   g_txo[NCFG][224];

// ---------------- packed f32x2 helpers ----------------
__device__ __forceinline__ unsigned long long f2pack(float lo, float hi) {
    unsigned long long r;
    asm("mov.b64 %0, {%1, %2};" : "=l"(r) : "f"(lo), "f"(hi));
    return r;
}
__device__ __forceinline__ void funpack(unsigned long long v, float& lo, float& hi) {
    asm("mov.b64 {%0, %1}, %2;" : "=f"(lo), "=f"(hi) : "l"(v));
}
__device__ __forceinline__ void ffma2(unsigned long long& d,
                                      unsigned long long a, unsigned long long b) {
    asm("fma.rn.f32x2 %0, %1, %2, %0;" : "+l"(d) : "l"(a), "l"(b));
}

__device__ __forceinline__ float2 pack_h4(float a, float b, float c) {
    union { float2 f; __half2 h[2]; } u;
    u.h[0] = __floats2half2_rn(a, b);
    u.h[1] = __floats2half2_rn(c, 0.0f);
    return u.f;
}

// ---------------------------------------------------------------------------
// Prep: blocks [0,6272) pad x to float4; blocks [6272,6314) compute taps.
// ---------------------------------------------------------------------------
__global__ void prep_kernel(const float* __restrict__ x) {
    if (blockIdx.x < 6272) {
        const int idx = blockIdx.x * 256 + threadIdx.x;   // < XN exactly
        const float* p = x + (size_t)idx * 3;
        g_x4[idx] = make_float4(p[0], p[1], p[2], 0.0f);
        return;
    }
    const int bi  = blockIdx.x - 6272;      // 0..41
    const int cfg = bi % NCFG;
    const int dim = bi / NCFG;              // 0 = rows(kh), 1 = cols(kw)
    const int o   = threadIdx.x;
    if (o >= 224) return;

    const int n  = dim ? c_kw[cfg] : c_kh[cfg];
    const int kw = c_kw[cfg];

    const double ks = (n > 224) ? (double)n / 224.0 : 1.0;
    const double sf = ((double)o + 0.5) * (double)n / 224.0 - 0.5;
    const int NT = (n < 224) ? 2 : (2 * n) / 224 + 1;   // 2..4
    int lo = (int)ceil(sf - ks);

    double w[4];
    double tot = 0.0;
    for (int t = 0; t < 4; ++t) {
        double v = 0.0;
        if (t < NT) {
            int j = lo + t;
            if (j >= 0 && j < n) {
                v = 1.0 - fabs(sf - (double)j) / ks;
                if (v < 0.0) v = 0.0;
            }
        }
        w[t] = v;
        tot += v;
    }
    const double r = 1.0 / tot;

    float wf[4];
    int   of[4];
    for (int t = 0; t < 4; ++t) {
        wf[t] = (float)(w[t] * r);
        int j = lo + t;
        if (j < 0) j = 0;
        if (j > n - 1) j = n - 1;
        of[t] = dim ? j : j * kw;
    }
    if (dim == 0) {
        g_tyw[cfg][o] = make_float4(wf[0], wf[1], wf[2], wf[3]);
        g_tyo[cfg][o] = make_int4(of[0], of[1], of[2], of[3]);
    } else {
        g_txw[cfg][o] = make_float4(wf[0], wf[1], wf[2], wf[3]);
        g_txo[cfg][o] = make_int4(of[0], of[1], of[2], of[3]);
    }
}

// ---------------------------------------------------------------------------
// Kernel A: each thread computes TWO vertically adjacent output pixels
// (i0, i0+1) x all 4 k x 3 ch with packed fp32x2 FFMA.
// ---------------------------------------------------------------------------
template<int S, int G, int A, int CFG0>
__global__ void agg_kernel(const float* __restrict__ wsrc) {
    const int cfg = CFG0 + blockIdx.z;
    const int kh = c_kh[cfg], kw = c_kw[cfg];
    const int area = kh * kw;
    const int hp = (kh + 1) >> 1;
    const int parea = hp * kw;
    if ((int)(blockIdx.x * blockDim.x) >= parea) return;

    const int a = blockIdx.z;
    const int b = blockIdx.y;
    constexpr int G2 = G * G;

    // prepacked broadcast weight pairs: swp[gh*4 + k] = (w,w)
    __shared__ unsigned long long swp[G2 * 4];
    {
        const float* wb = wsrc + (size_t)(b * A + a) * 4 * G2;
        for (int t = threadIdx.x; t < 4 * G2; t += blockDim.x) {
            const int gh = t >> 2, k = t & 3;
            const float v = wb[k * G2 + gh];
            swp[t] = f2pack(v, v);
        }
    }
    __syncthreads();

    const int idx = blockIdx.x * blockDim.x + threadIdx.x;
    if (idx >= parea) return;

    const int ip = idx / kw;
    const int j  = idx - ip * kw;
    const int i0 = 2 * ip;
    const bool has1 = (i0 + 1) < kh;

    const int p0 = (kh - S + 1) >> 1;
    const int p1 = (kw - S + 1) >> 1;
    const int ri = i0 - p0;                  // x row of pixel0 = g*S + ri
    const int cj = j - p1;                   // x col = h*S + cj

    // g union bounds: need row1 = g*S+ri+1 >= 0 and row0 = g*S+ri <= 447
    const int tlo = -ri - 1;
    const int glo = (tlo <= 0) ? 0 : (tlo + S - 1) / S;
    const int ghi = min(G - 1, (447 - ri) / S);
    const int hmin = (cj >= 0) ? 0 : (-cj + S - 1) / S;
    const int hmax = min(G - 1, (447 - cj) / S);

    unsigned long long acc[12];   // [k][ch], each = (pixel0, pixel1)
#pragma unroll
    for (int t = 0; t < 12; ++t) acc[t] = 0ull;

    const float4 zf4 = make_float4(0.f, 0.f, 0.f, 0.f);

    for (int g = glo; g <= ghi; ++g) {
        const int r0 = g * S + ri;
        const bool v0 = (r0 >= 0);                        // r0 <= 447 by ghi
        const bool v1 = has1 && (r0 + 1 <= 447);          // r0+1 >= 0 by glo
        const float4* xr0 = g_x4 + ((size_t)(b * 448 + r0)) * 448 + cj;
        const unsigned long long* wg = swp + g * G * 4;
#pragma unroll 4
        for (int h = hmin; h <= hmax; ++h) {
            const float4 x0 = v0 ? __ldg(xr0 + h * S)       : zf4;
            const float4 x1 = v1 ? __ldg(xr0 + 448 + h * S) : zf4;
            const unsigned long long B0 = f2pack(x0.x, x1.x);
            const unsigned long long B1 = f2pack(x0.y, x1.y);
            const unsigned long long B2 = f2pack(x0.z, x1.z);
            const unsigned long long* wp = wg + h * 4;
#pragma unroll
            for (int k = 0; k < 4; ++k) {
                const unsigned long long wk = wp[k];
                ffma2(acc[k * 3 + 0], wk, B0);
                ffma2(acc[k * 3 + 1], wk, B1);
                ffma2(acc[k * 3 + 2], wk, B2);
            }
        }
    }

    float2* dst = g_aggh + (size_t)32 * c_off[cfg] + (size_t)(b * 4) * area
                + (size_t)i0 * kw + j;
#pragma unroll
    for (int k = 0; k < 4; ++k) {
        float c00, c01, c10, c11, c20, c21;
        funpack(acc[k * 3 + 0], c00, c01);
        funpack(acc[k * 3 + 1], c10, c11);
        funpack(acc[k * 3 + 2], c20, c21);
        float2* d = dst + (size_t)k * area;
        __stcs(d, pack_h4(c00, c10, c20));
        if (has1) __stcs(d + kw, pack_h4(c01, c11, c21));
    }
}

// ---------------------------------------------------------------------------
// Kernel B: fully unrolled per-cfg separable resize accumulation (half4 loads).
// ---------------------------------------------------------------------------
template<int AREA, int OFF, int NR, int NC>
__device__ __forceinline__ void do_cfg(int cfg, int bk, int ox,
                                       const float (*s_yw)[4], const int (*s_yo)[4],
                                       float& a0, float& a1, float& a2) {
    const float2* base = g_aggh + (size_t)32 * OFF + (size_t)bk * AREA;
    const float4 xw = g_txw[cfg][ox];
    const int4   xo = g_txo[cfg][ox];
    const float xwv[4] = {xw.x, xw.y, xw.z, xw.w};
    const int   xov[4] = {xo.x, xo.y, xo.z, xo.w};
#pragma unroll
    for (int r = 0; r < NR; ++r) {
        const float wy = s_yw[cfg][r];
        const float2* p = base + s_yo[cfg][r];
#pragma unroll
        for (int c = 0; c < NC; ++c) {
            const float w = wy * xwv[c];
            union { float2 f; __half2 h[2]; } u;
            u.f = __ldg(p + xov[c]);
            const float2 lo = __half22float2(u.h[0]);
            const float  hi = __low2float(u.h[1]);
            a0 += w * lo.x;
            a1 += w * lo.y;
            a2 += w * hi;
        }
    }
}

__global__ void __launch_bounds__(224) resize_kernel(float* __restrict__ out) {
    const int oy = blockIdx.x;
    const int bk = blockIdx.y;
    const int ox = threadIdx.x;

    __shared__ float s_yw[NCFG][4];
    __shared__ int   s_yo[NCFG][4];
    {
        const int t = threadIdx.x;
        if (t < NCFG * 4) {
            const int cfg = t >> 2, k = t & 3;
            s_yw[cfg][k] = ((const float*)&g_tyw[cfg][oy])[k];
            s_yo[cfg][k] = ((const int*)&g_tyo[cfg][oy])[k];
        }
    }
    __syncthreads();

    float a0 = 0.0f, a1 = 0.0f, a2 = 0.0f;

    do_cfg< 3626,      0, 2, 2>( 0, bk, ox, s_yw, s_yo, a0, a1, a2);
    do_cfg< 3600,   3626, 2, 2>( 1, bk, ox, s_yw, s_yo, a0, a1, a2);
    do_cfg< 3626,   7226, 2, 2>( 2, bk, ox, s_yw, s_yo, a0, a1, a2);
    do_cfg< 5766,  10852, 2, 2>( 3, bk, ox, s_yw, s_yo, a0, a1, a2);
    do_cfg< 5776,  16618, 2, 2>( 4, bk, ox, s_yw, s_yo, a0, a1, a2);
    do_cfg< 5766,  22394, 2, 2>( 5, bk, ox, s_yw, s_yo, a0, a1, a2);
    do_cfg<14504,  28160, 2, 2>( 6, bk, ox, s_yw, s_yo, a0, a1, a2);
    do_cfg<14400,  42664, 2, 2>( 7, bk, ox, s_yw, s_yo, a0, a1, a2);
    do_cfg<14504,  57064, 2, 2>( 8, bk, ox, s_yw, s_yo, a0, a1, a2);
    do_cfg<23064,  71568, 2, 2>( 9, bk, ox, s_yw, s_yo, a0, a1, a2);
    do_cfg<23104,  94632, 2, 2>(10, bk, ox, s_yw, s_yo, a0, a1, a2);
    do_cfg<23064, 117736, 2, 2>(11, bk, ox, s_yw, s_yo, a0, a1, a2);
    do_cfg<36660, 140800, 3, 2>(12, bk, ox, s_yw, s_yo, a0, a1, a2);
    do_cfg<36864, 177460, 2, 2>(13, bk, ox, s_yw, s_yo, a0, a1, a2);
    do_cfg<36660, 214324, 2, 3>(14, bk, ox, s_yw, s_yo, a0, a1, a2);
    do_cfg<58312, 250984, 3, 2>(15, bk, ox, s_yw, s_yo, a0, a1, a2);
    do_cfg<58081, 309296, 3, 3>(16, bk, ox, s_yw, s_yo, a0, a1, a2);
    do_cfg<58312, 367377, 2, 3>(17, bk, ox, s_yw, s_yo, a0, a1, a2);
    do_cfg<92504, 425689, 4, 3>(18, bk, ox, s_yw, s_yo, a0, a1, a2);
    do_cfg<92416, 518193, 3, 3>(19, bk, ox, s_yw, s_yo, a0, a1, a2);
    do_cfg<92504, 610609, 3, 4>(20, bk, ox, s_yw, s_yo, a0, a1, a2);

    float* o = out + ((size_t)(bk * 224 + oy) * 224 + ox) * 3;
    o[0] = a0;
    o[1] = a1;
    o[2] = a2;
}

// ---------------------------------------------------------------------------
extern "C" void kernel_launch(void* const* d_in, const int* in_sizes, int n_in,
                              void* d_out, int out_size) {
    const float* x  = (const float*)d_in[0];
    const float* w3 = (const float*)d_in[1];
    const float* w4 = (const float*)d_in[2];
    const float* w5 = (const float*)d_in[3];

    prep_kernel<<<6272 + 42, 256>>>(x);

    // max pair-areas: p3 2914 -> 12 blocks; p4 11552 -> 46; p5 46376 -> 182
    agg_kernel<32, 14, 6, 0><<<dim3(12, 8, 6), 256>>>(w3);
    agg_kernel<64, 7, 6, 6><<<dim3(46, 8, 6), 256>>>(w4);
    agg_kernel<128, 4, 9, 12><<<dim3(182, 8, 9), 256>>>(w5);

    dim3 gridB(224, 32);
    resize_kernel<<<gridB, 224>>>((float*)d_out);
}

// round 8
// speedup vs baseline: 1.2361x; 1.2361x over previous
#include <cuda_runtime.h>
#include <cuda_fp16.h>

#define NCFG 21

__constant__ int c_kh[NCFG] = {74,60,49,93,76,62, 148,120,98,186,152,124,
                               235,192,156,296,241,197,373,304,248};
__constant__ int c_kw[NCFG] = {49,60,74,62,76,93, 98,120,148,124,152,186,
                               156,192,235,197,241,296,248,304,373};
__constant__ int c_off[NCFG] = {0,3626,7226,10852,16618,22394,
                                28160,42664,57064,71568,94632,117736,
                                140800,177460,214324,250984,309296,367377,
                                425689,518193,610609};
// total area = 703113 pixels; scratch: [cfg][bk(32)][pixel], half4 packed in float2
#define TOTAL_AGG 22499616
__device__ float2 g_aggh[TOTAL_AGG];   // 180 MB

// x padded to float4 with guard margins: [b][y][x] (8*448*448 float4) + 1024 each side
#define XN 1605632
#define GUARD 1024
__device__ float4 g_x4g[XN + 2 * GUARD];

// Tap tables
__device__ float4 g_tyw[NCFG][224];
__device__ int4   g_tyo[NCFG][224];
__device__ float4 g_txw[NCFG][224];
__device__ int4   g_txo[NCFG][224];

// ---------------- packed f32x2 helpers ----------------
__device__ __forceinline__ unsigned long long f2pack(float lo, float hi) {
    unsigned long long r;
    asm("mov.b64 %0, {%1, %2};" : "=l"(r) : "f"(lo), "f"(hi));
    return r;
}
__device__ __forceinline__ void funpack(unsigned long long v, float& lo, float& hi) {
    asm("mov.b64 {%0, %1}, %2;" : "=f"(lo), "=f"(hi) : "l"(v));
}
__device__ __forceinline__ void ffma2(unsigned long long& d,
                                      unsigned long long a, unsigned long long b) {
    asm("fma.rn.f32x2 %0, %1, %2, %0;" : "+l"(d) : "l"(a), "l"(b));
}

__device__ __forceinline__ float2 pack_h4(float a, float b, float c) {
    union { float2 f; __half2 h[2]; } u;
    u.h[0] = __floats2half2_rn(a, b);
    u.h[1] = __floats2half2_rn(c, 0.0f);
    return u.f;
}

// ---------------------------------------------------------------------------
// Prep: blocks [0,6272) pad x to float4; blocks [6272,6314) compute taps.
// ---------------------------------------------------------------------------
__global__ void prep_kernel(const float* __restrict__ x) {
    if (blockIdx.x < 6272) {
        const int idx = blockIdx.x * 256 + threadIdx.x;   // < XN exactly
        const float* p = x + (size_t)idx * 3;
        g_x4g[GUARD + idx] = make_float4(p[0], p[1], p[2], 0.0f);
        return;
    }
    const int bi  = blockIdx.x - 6272;      // 0..41
    const int cfg = bi % NCFG;
    const int dim = bi / NCFG;              // 0 = rows(kh), 1 = cols(kw)
    const int o   = threadIdx.x;
    if (o >= 224) return;

    const int n  = dim ? c_kw[cfg] : c_kh[cfg];
    const int kw = c_kw[cfg];

    const double ks = (n > 224) ? (double)n / 224.0 : 1.0;
    const double sf = ((double)o + 0.5) * (double)n / 224.0 - 0.5;
    const int NT = (n < 224) ? 2 : (2 * n) / 224 + 1;   // 2..4
    int lo = (int)ceil(sf - ks);

    double w[4];
    double tot = 0.0;
    for (int t = 0; t < 4; ++t) {
        double v = 0.0;
        if (t < NT) {
            int j = lo + t;
            if (j >= 0 && j < n) {
                v = 1.0 - fabs(sf - (double)j) / ks;
                if (v < 0.0) v = 0.0;
            }
        }
        w[t] = v;
        tot += v;
    }
    const double r = 1.0 / tot;

    float wf[4];
    int   of[4];
    for (int t = 0; t < 4; ++t) {
        wf[t] = (float)(w[t] * r);
        int j = lo + t;
        if (j < 0) j = 0;
        if (j > n - 1) j = n - 1;
        of[t] = dim ? j : j * kw;
    }
    if (dim == 0) {
        g_tyw[cfg][o] = make_float4(wf[0], wf[1], wf[2], wf[3]);
        g_tyo[cfg][o] = make_int4(of[0], of[1], of[2], of[3]);
    } else {
        g_txw[cfg][o] = make_float4(wf[0], wf[1], wf[2], wf[3]);
        g_txo[cfg][o] = make_int4(of[0], of[1], of[2], of[3]);
    }
}

// ---------------------------------------------------------------------------
// Kernel A for p3/p4 (R6 structure): one float4 x load + one float4 weight
// load feeds 12 FFMAs (4 k x 3 ch). Streaming half4 stores.
// ---------------------------------------------------------------------------
template<int S, int G, int A, int CFG0>
__global__ void agg_kernel(const float* __restrict__ wsrc) {
    const int cfg = CFG0 + blockIdx.z;
    const int kh = c_kh[cfg], kw = c_kw[cfg];
    const int area = kh * kw;
    if ((int)(blockIdx.x * blockDim.x) >= area) return;

    const int a = blockIdx.z;
    const int b = blockIdx.y;
    constexpr int G2 = G * G;

    __shared__ float4 sw4[G2];              // [g*G+h] -> weights for 4 k
    {
        float* swf = (float*)sw4;
        const float* wb = wsrc + (size_t)(b * A + a) * 4 * G2;
        for (int t = threadIdx.x; t < 4 * G2; t += blockDim.x) {
            const int gh = t >> 2, k = t & 3;
            swf[t] = wb[k * G2 + gh];
        }
    }
    __syncthreads();

    const int idx = blockIdx.x * blockDim.x + threadIdx.x;
    if (idx >= area) return;

    const int i = idx / kw;
    const int j = idx - i * kw;
    const int p0 = (kh - S + 1) >> 1;
    const int p1 = (kw - S + 1) >> 1;
    const int ri = i - p0;                  // x row = g*S + ri
    const int cj = j - p1;                  // x col = h*S + cj

    const int gmin = (ri >= 0) ? 0 : (-ri + S - 1) / S;
    const int gmax = min(G - 1, (447 - ri) / S);
    const int hmin = (cj >= 0) ? 0 : (-cj + S - 1) / S;
    const int hmax = min(G - 1, (447 - cj) / S);

    float a00=0,a01=0,a02=0, a10=0,a11=0,a12=0,
          a20=0,a21=0,a22=0, a30=0,a31=0,a32=0;

    for (int g = gmin; g <= gmax; ++g) {
        const float4* xrow = g_x4g + GUARD + (size_t)(b * 448 + g * S + ri) * 448 + cj;
        const float4* swg  = sw4 + g * G;
#pragma unroll 4
        for (int h = hmin; h <= hmax; ++h) {
            const float4 xv = __ldg(xrow + h * S);
            const float4 wv = swg[h];
            a00 += wv.x * xv.x; a01 += wv.x * xv.y; a02 += wv.x * xv.z;
            a10 += wv.y * xv.x; a11 += wv.y * xv.y; a12 += wv.y * xv.z;
            a20 += wv.z * xv.x; a21 += wv.z * xv.y; a22 += wv.z * xv.z;
            a30 += wv.w * xv.x; a31 += wv.w * xv.y; a32 += wv.w * xv.z;
        }
    }

    float2* dst = g_aggh + (size_t)32 * c_off[cfg] + (size_t)(b * 4) * area + idx;
    __stcs(dst,                    pack_h4(a00, a01, a02));
    __stcs(dst + (size_t)area,     pack_h4(a10, a11, a12));
    __stcs(dst + (size_t)2 * area, pack_h4(a20, a21, a22));
    __stcs(dst + (size_t)3 * area, pack_h4(a30, a31, a32));
}

// ---------------------------------------------------------------------------
// Specialized p5 (S=128, G=4): division-free mapping, block-uniform row,
// fully unrolled 4x4 taps with immediate-offset loads, FSEL column masks,
// channel-packed FFMA2.
// grid = (2, 8*373, 9), block = 256 (one row segment).
// ---------------------------------------------------------------------------
__global__ void __launch_bounds__(256) agg5_kernel(const float* __restrict__ w5) {
    const int cfg = 12 + blockIdx.z;
    const int kh = c_kh[cfg], kw = c_kw[cfg];
    const int by = blockIdx.y;
    const int b  = by / 373;
    const int i  = by - b * 373;
    if (i >= kh) return;                      // block-uniform
    const int j0 = blockIdx.x * 256;
    if (j0 >= kw) return;                     // block-uniform

    __shared__ unsigned long long swp[64];    // [(g*4+h)*4 + k] = (w,w)
    {
        const int t = threadIdx.x;
        if (t < 64) {
            const int gh = t >> 2, k = t & 3;
            const float v = w5[((size_t)(b * 9 + blockIdx.z) * 4 + k) * 16 + gh];
            swp[t] = f2pack(v, v);
        }
    }
    __syncthreads();

    const int j = j0 + threadIdx.x;
    if (j >= kw) return;

    const int p0 = (kh - 127) >> 1;
    const int p1 = (kw - 127) >> 1;
    const int ri = i - p0;
    const int cj = j - p1;

    bool hv[4];
#pragma unroll
    for (int h = 0; h < 4; ++h)
        hv[h] = (unsigned)(cj + h * 128) <= 447u;

    unsigned long long acc01[4] = {0ull, 0ull, 0ull, 0ull};
    unsigned long long acc2p[4] = {0ull, 0ull, 0ull, 0ull};

    const float4* base = g_x4g + GUARD + ((long long)(b * 448) + ri) * 448 + cj;

#pragma unroll
    for (int g = 0; g < 4; ++g) {
        const int r = g * 128 + ri;
        if ((unsigned)r <= 447u) {            // uniform across block
            float4 xv[4];
#pragma unroll
            for (int h = 0; h < 4; ++h)
                xv[h] = __ldg(base + g * (128 * 448) + h * 128);
#pragma unroll
            for (int h = 0; h < 4; ++h) {
                const float x0 = hv[h] ? xv[h].x : 0.0f;
                const float x1 = hv[h] ? xv[h].y : 0.0f;
                const float x2 = hv[h] ? xv[h].z : 0.0f;
                const unsigned long long x01 = f2pack(x0, x1);
                const unsigned long long x2w = f2pack(x2, 0.0f);
                const unsigned long long* wp = swp + (g * 4 + h) * 4;
#pragma unroll
                for (int k = 0; k < 4; ++k) {
                    const unsigned long long wk = wp[k];
                    ffma2(acc01[k], wk, x01);
                    ffma2(acc2p[k], wk, x2w);
                }
            }
        }
    }

    const int area = kh * kw;
    float2* dst = g_aggh + (size_t)32 * c_off[cfg] + (size_t)(b * 4) * area
                + (size_t)i * kw + j;
#pragma unroll
    for (int k = 0; k < 4; ++k) {
        float c0, c1, c2, cw;
        funpack(acc01[k], c0, c1);
        funpack(acc2p[k], c2, cw);
        __stcs(dst + (size_t)k * area, pack_h4(c0, c1, c2));
    }
}

// ---------------------------------------------------------------------------
// Kernel B: fully unrolled per-cfg separable resize accumulation (half4 loads).
// ---------------------------------------------------------------------------
template<int AREA, int OFF, int NR, int NC>
__device__ __forceinline__ void do_cfg(int cfg, int bk, int ox,
                                       const float (*s_yw)[4], const int (*s_yo)[4],
                                       float& a0, float& a1, float& a2) {
    const float2* base = g_aggh + (size_t)32 * OFF + (size_t)bk * AREA;
    const float4 xw = g_txw[cfg][ox];
    const int4   xo = g_txo[cfg][ox];
    const float xwv[4] = {xw.x, xw.y, xw.z, xw.w};
    const int   xov[4] = {xo.x, xo.y, xo.z, xo.w};
#pragma unroll
    for (int r = 0; r < NR; ++r) {
        const float wy = s_yw[cfg][r];
        const float2* p = base + s_yo[cfg][r];
#pragma unroll
        for (int c = 0; c < NC; ++c) {
            const float w = wy * xwv[c];
            union { float2 f; __half2 h[2]; } u;
            u.f = __ldg(p + xov[c]);
            const float2 lo = __half22float2(u.h[0]);
            const float  hi = __low2float(u.h[1]);
            a0 += w * lo.x;
            a1 += w * lo.y;
            a2 += w * hi;
        }
    }
}

__global__ void __launch_bounds__(224) resize_kernel(float* __restrict__ out) {
    const int oy = blockIdx.x;
    const int bk = blockIdx.y;
    const int ox = threadIdx.x;

    __shared__ float s_yw[NCFG][4];
    __shared__ int   s_yo[NCFG][4];
    {
        const int t = threadIdx.x;
        if (t < NCFG * 4) {
            const int cfg = t >> 2, k = t & 3;
            s_yw[cfg][k] = ((const float*)&g_tyw[cfg][oy])[k];
            s_yo[cfg][k] = ((const int*)&g_tyo[cfg][oy])[k];
        }
    }
    __syncthreads();

    float a0 = 0.0f, a1 = 0.0f, a2 = 0.0f;

    do_cfg< 3626,      0, 2, 2>( 0, bk, ox, s_yw, s_yo, a0, a1, a2);
    do_cfg< 3600,   3626, 2, 2>( 1, bk, ox, s_yw, s_yo, a0, a1, a2);
    do_cfg< 3626,   7226, 2, 2>( 2, bk, ox, s_yw, s_yo, a0, a1, a2);
    do_cfg< 5766,  10852, 2, 2>( 3, bk, ox, s_yw, s_yo, a0, a1, a2);
    do_cfg< 5776,  16618, 2, 2>( 4, bk, ox, s_yw, s_yo, a0, a1, a2);
    do_cfg< 5766,  22394, 2, 2>( 5, bk, ox, s_yw, s_yo, a0, a1, a2);
    do_cfg<14504,  28160, 2, 2>( 6, bk, ox, s_yw, s_yo, a0, a1, a2);
    do_cfg<14400,  42664, 2, 2>( 7, bk, ox, s_yw, s_yo, a0, a1, a2);
    do_cfg<14504,  57064, 2, 2>( 8, bk, ox, s_yw, s_yo, a0, a1, a2);
    do_cfg<23064,  71568, 2, 2>( 9, bk, ox, s_yw, s_yo, a0, a1, a2);
    do_cfg<23104,  94632, 2, 2>(10, bk, ox, s_yw, s_yo, a0, a1, a2);
    do_cfg<23064, 117736, 2, 2>(11, bk, ox, s_yw, s_yo, a0, a1, a2);
    do_cfg<36660, 140800, 3, 2>(12, bk, ox, s_yw, s_yo, a0, a1, a2);
    do_cfg<36864, 177460, 2, 2>(13, bk, ox, s_yw, s_yo, a0, a1, a2);
    do_cfg<36660, 214324, 2, 3>(14, bk, ox, s_yw, s_yo, a0, a1, a2);
    do_cfg<58312, 250984, 3, 2>(15, bk, ox, s_yw, s_yo, a0, a1, a2);
    do_cfg<58081, 309296, 3, 3>(16, bk, ox, s_yw, s_yo, a0, a1, a2);
    do_cfg<58312, 367377, 2, 3>(17, bk, ox, s_yw, s_yo, a0, a1, a2);
    do_cfg<92504, 425689, 4, 3>(18, bk, ox, s_yw, s_yo, a0, a1, a2);
    do_cfg<92416, 518193, 3, 3>(19, bk, ox, s_yw, s_yo, a0, a1, a2);
    do_cfg<92504, 610609, 3, 4>(20, bk, ox, s_yw, s_yo, a0, a1, a2);

    float* o = out + ((size_t)(bk * 224 + oy) * 224 + ox) * 3;
    o[0] = a0;
    o[1] = a1;
    o[2] = a2;
}

// ---------------------------------------------------------------------------
extern "C" void kernel_launch(void* const* d_in, const int* in_sizes, int n_in,
                              void* d_out, int out_size) {
    const float* x  = (const float*)d_in[0];
    const float* w3 = (const float*)d_in[1];
    const float* w4 = (const float*)d_in[2];
    const float* w5 = (const float*)d_in[3];

    prep_kernel<<<6272 + 42, 256>>>(x);

    // p3: max area 5776 -> 23 blocks; p4: 23104 -> 91 blocks (R6 structure)
    agg_kernel<32, 14, 6, 0><<<dim3(23, 8, 6), 256>>>(w3);
    agg_kernel<64, 7, 6, 6><<<dim3(91, 8, 6), 256>>>(w4);
    // p5 specialized: rows in grid.y (8 batches x up to 373 rows), 2 col segments
    agg5_kernel<<<dim3(2, 8 * 373, 9), 256>>>(w5);

    dim3 gridB(224, 32);
    resize_kernel<<<gridB, 224>>>((float*)d_out);
}